// round 5
// baseline (speedup 1.0000x reference)
#include <cuda_runtime.h>
#include <cuda_bf16.h>
#include <cstdint>

// ===== problem constants =====
#define NP   65536
#define KC   1024
#define DIM  64

// ===== output layout (concatenated reference tuple, float32) =====
#define OFF_LOSS  4194304
#define OFF_IDX   4194305
#define OFF_CNT   4259841
#define OFF_AVG   4260865
#define OUT_FULL  4326401

// ===== device scratch =====
__device__ int      g_idx[NP];
__device__ int      g_cnt[KC];
__device__ float    g_avg[KC * DIM];
__device__ float    g_loss;
__device__ float    g_w2[KC];
__device__ int      g_ncand[NP];
__device__ uint32_t g_cand[NP * 16];
// W split fragments, mma-fragment-linear: [nblk(4)][kstep(24)][n16grp(16)][lane(32)][16B]
__device__ uint4 g_wfrag[49152];   // 786432 bytes

// ===== smem layout of argmin kernel (bytes) =====
#define SMA     0        // A frags (3-level concat): 12*8*32*16 = 49152
#define SMB     49152    // B double buffer: 2*32768
#define SMW2    114688   // 1024 f
#define SMSR    118784   // 128 f
#define SMBEST  119296   // 128 ull
#define SMNC    120320   // 128 u32
#define SMCAND  120832   // 128*16 u32
#define SMEM_TOTAL 129024

// candidate threshold: 8 ulp at the s~64 binade
#define CAND_EPS 6.2e-5f

// pair schedules for the 6 split products:
//   p:      0     1     2     3     4     5
//   A lvl:  h(0)  h(0)  m(1)  h(0)  l(2)  m(1)
//   B lvl:  h(0)  m(1)  h(0)  l(2)  h(0)  m(1)
__device__ __forceinline__ int pairA_of(int p) { return (p == 4) ? 2 : ((p == 2 || p == 5) ? 1 : 0); }
__device__ __forceinline__ int pairB_of(int p) { return (p == 3) ? 2 : (p & 1); }

// 3-level bf16 split (residuals exact in fp32)
__device__ __forceinline__ void split3(float x, unsigned short& h,
                                       unsigned short& m, unsigned short& l) {
    __nv_bfloat16 b = __float2bfloat16_rn(x);
    h = __bfloat16_as_ushort(b);
    float r = x - __bfloat162float(b);
    b = __float2bfloat16_rn(r);
    m = __bfloat16_as_ushort(b);
    r = r - __bfloat162float(b);
    l = __bfloat16_as_ushort(__float2bfloat16_rn(r));
}
__device__ __forceinline__ unsigned short split_lvl(float x, int lvl) {
    unsigned short h, m, l;
    split3(x, h, m, l);
    return lvl == 0 ? h : (lvl == 1 ? m : l);
}

__device__ __forceinline__ uint32_t smem_to_u32(const void* p) {
    uint32_t a;
    asm("{ .reg .u64 t; cvta.to.shared.u64 t, %1; cvt.u32.u64 %0, t; }" : "=r"(a) : "l"(p));
    return a;
}
#define CP_ASYNC16(dst, src) \
    asm volatile("cp.async.cg.shared.global [%0], [%1], 16;" :: "r"(dst), "l"(src) : "memory")
#define CP_COMMIT() asm volatile("cp.async.commit_group;" ::: "memory")
#define CP_WAIT1()  asm volatile("cp.async.wait_group 1;" ::: "memory")
#define CP_WAIT0()  asm volatile("cp.async.wait_group 0;" ::: "memory")

#define MMA16816(d, a, b0v, b1v) \
    asm volatile("mma.sync.aligned.m16n8k16.row.col.f32.bf16.bf16.f32 " \
        "{%0,%1,%2,%3}, {%4,%5,%6,%7}, {%8,%9}, {%0,%1,%2,%3};" \
        : "+f"((d)[0]), "+f"((d)[1]), "+f"((d)[2]), "+f"((d)[3]) \
        : "r"((a).x), "r"((a).y), "r"((a).z), "r"((a).w), "r"(b0v), "r"(b1v))

// ---------------------------------------------------------------------------
// Prep: zero accumulators; w2 (sequential fp32 rounding); W split fragments
// into pair-scheduled fragment-linear gmem layout (coalesced u32 stores).
__global__ void prep_kernel(const float* __restrict__ W) {
    const int t = blockIdx.x * blockDim.x + threadIdx.x;
    if (t < 196608) {
        const int reg   = t & 3;
        const int lane  = (t >> 2) & 31;
        const int group = (t >> 7) & 15;
        const int rest  = t >> 11;                 // nblk*24 + kstep
        const int kstep = rest % 24;
        const int nblk  = rest / 24;
        const int pair  = kstep >> 2;
        const int lvlb  = pairB_of(pair);
        const int n     = (lane >> 2) + ((reg & 2) ? 8 : 0);
        const int code  = nblk * 256 + group * 16 + n;
        const int d     = ((kstep & 3) << 4) + ((reg & 1) << 3) + ((lane & 3) << 1);
        const float x0 = W[code * DIM + d];
        const float x1 = W[code * DIM + d + 1];
        uint32_t v = (uint32_t)split_lvl(x0, lvlb) |
                     ((uint32_t)split_lvl(x1, lvlb) << 16);
        ((uint32_t*)g_wfrag)[t] = v;
    }
    if (t < KC) {
        const float* wr = W + (size_t)t * DIM;
        float s = 0.0f;
        #pragma unroll 8
        for (int d = 0; d < DIM; d++) s = __fadd_rn(s, __fmul_rn(wr[d], wr[d]));
        g_w2[t] = s;
        g_cnt[t] = 0;
    }
    if (t < KC * DIM) g_avg[t] = 0.0f;
    if (t == 0)       g_loss   = 0.0f;
}

// ---------------------------------------------------------------------------
// Argmin phase 1: 6-product split-bf16 GEMM via mma.sync (HMMA); produces a
// per-row candidate list (codes within CAND_EPS of the row minimum).
__global__ void __launch_bounds__(256)
argmin_kernel(const float* __restrict__ Z) {
    extern __shared__ char smem[];
    const uint32_t sb = smem_to_u32(smem);
    const int tid  = threadIdx.x;
    const int lane = tid & 31;
    const int wm   = (tid >> 5) >> 2;      // 0..1
    const int wn   = (tid >> 5) & 3;       // 0..3
    const int n0   = blockIdx.x * 128;

    uint32_t*           As   = (uint32_t*)(smem + SMA);
    float*              w2s  = (float*)(smem + SMW2);
    float*              srow = (float*)(smem + SMSR);
    unsigned long long* best = (unsigned long long*)(smem + SMBEST);
    uint32_t*           ncnd = (uint32_t*)(smem + SMNC);
    uint32_t*           cand = (uint32_t*)(smem + SMCAND);

    // --- prologue: A splits (3-level concat, ksteps 0..11) in fragment order ---
    const float2* Zv = (const float2*)(Z + (size_t)n0 * DIM);
    for (int i = tid; i < 4096; i += 256) {          // 128 rows x 32 float2
        const int m = i >> 5, j = i & 31, d0 = j * 2;
        float2 v = Zv[i];
        unsigned short h0, m0, l0, h1, m1, l1;
        split3(v.x, h0, m0, l0);
        split3(v.y, h1, m1, l1);
        uint32_t packed[3] = {
            (uint32_t)h0 | ((uint32_t)h1 << 16),
            (uint32_t)m0 | ((uint32_t)m1 << 16),
            (uint32_t)l0 | ((uint32_t)l1 << 16) };
        const int rm = m & 15;
        const int ln = ((rm & 7) << 2) | ((d0 & 7) >> 1);
        const int rg = (rm >> 3) + (((d0 >> 3) & 1) << 1);
        #pragma unroll
        for (int lvl = 0; lvl < 3; lvl++) {
            const int ks = lvl * 4 + (d0 >> 4);      // 0..11
            As[((ks * 8 + (m >> 4)) * 32 + ln) * 4 + rg] = packed[lvl];
        }
    }
    for (int i = tid; i < KC; i += 256) w2s[i] = g_w2[i];
    if (tid < 128) {
        const float* zr = Z + (size_t)(n0 + tid) * DIM;
        float s = 0.0f;
        #pragma unroll 8
        for (int d = 0; d < DIM; d++) s = __fadd_rn(s, __fmul_rn(zr[d], zr[d]));
        srow[tid] = s;
        best[tid] = ~0ull;
        ncnd[tid] = 0;
    }
    __syncthreads();

    // --- prefetch chunk 0 ---
    const char* gB = (const char*)g_wfrag;
    {
        uint32_t dst = sb + SMB;
        const char* src = gB;
        #pragma unroll
        for (int p = 0; p < 8; p++)
            CP_ASYNC16(dst + (tid + p * 256) * 16, src + (tid + p * 256) * 16);
        CP_COMMIT();
    }

    float acc[4][8][4];

    for (int it = 0; it < 24; it++) {
        const int nb = it / 6, kc = it % 6;
        const int lvlA = pairA_of(kc);
        if (kc == 0) {
            #pragma unroll
            for (int a = 0; a < 4; a++)
                #pragma unroll
                for (int b = 0; b < 8; b++)
                    #pragma unroll
                    for (int c = 0; c < 4; c++) acc[a][b][c] = 0.0f;
        }
        if (it + 1 < 24) {
            uint32_t dst = sb + SMB + ((it + 1) & 1) * 32768;
            const char* src = gB + (size_t)(it + 1) * 32768;
            #pragma unroll
            for (int p = 0; p < 8; p++)
                CP_ASYNC16(dst + (tid + p * 256) * 16, src + (tid + p * 256) * 16);
            CP_COMMIT();
            CP_WAIT1();
        } else {
            CP_WAIT0();
        }
        __syncthreads();

        const uint4* Bb = (const uint4*)(smem + SMB + (it & 1) * 32768);
        const uint4* Ab = (const uint4*)(smem + SMA);
        #pragma unroll
        for (int ks = 0; ks < 4; ks++) {
            uint4 af[4], bf[4];
            #pragma unroll
            for (int mt = 0; mt < 4; mt++)
                af[mt] = Ab[(((lvlA * 4 + ks) * 8) + wm * 4 + mt) * 32 + lane];
            #pragma unroll
            for (int g = 0; g < 4; g++)
                bf[g] = Bb[(ks * 16 + wn * 4 + g) * 32 + lane];
            #pragma unroll
            for (int mt = 0; mt < 4; mt++)
                #pragma unroll
                for (int g = 0; g < 4; g++) {
                    MMA16816(acc[mt][2 * g],     af[mt], bf[g].x, bf[g].y);
                    MMA16816(acc[mt][2 * g + 1], af[mt], bf[g].z, bf[g].w);
                }
        }

        if (kc == 5) {
            // --- phase 1: per-row running min ---
            const float* w2p = w2s + nb * 256;
            #pragma unroll
            for (int mt = 0; mt < 4; mt++) {
                const int r1 = wm * 64 + mt * 16 + (lane >> 2);
                const float s1 = srow[r1], s2 = srow[r1 + 8];
                unsigned long long p1 = ~0ull, p2 = ~0ull;
                #pragma unroll
                for (int gg = 0; gg < 8; gg++) {
                    const int c0 = wn * 64 + (gg >> 1) * 16 + ((gg & 1) << 3) + ((lane & 3) << 1);
                    const float w20 = w2p[c0], w21 = w2p[c0 + 1];
                    const uint32_t k0 = (uint32_t)(nb * 256 + c0);
                    float d0 = __fadd_rn(__fadd_rn(s1, __fmul_rn(-2.0f, acc[mt][gg][0])), w20);
                    float d1 = __fadd_rn(__fadd_rn(s1, __fmul_rn(-2.0f, acc[mt][gg][1])), w21);
                    float d2 = __fadd_rn(__fadd_rn(s2, __fmul_rn(-2.0f, acc[mt][gg][2])), w20);
                    float d3 = __fadd_rn(__fadd_rn(s2, __fmul_rn(-2.0f, acc[mt][gg][3])), w21);
                    unsigned long long q;
                    q = ((unsigned long long)__float_as_uint(d0) << 32) | k0;       if (q < p1) p1 = q;
                    q = ((unsigned long long)__float_as_uint(d1) << 32) | (k0 + 1); if (q < p1) p1 = q;
                    q = ((unsigned long long)__float_as_uint(d2) << 32) | k0;       if (q < p2) p2 = q;
                    q = ((unsigned long long)__float_as_uint(d3) << 32) | (k0 + 1); if (q < p2) p2 = q;
                }
                #pragma unroll
                for (int o = 1; o < 4; o <<= 1) {
                    unsigned long long q1 = __shfl_xor_sync(0xffffffffu, p1, o);
                    unsigned long long q2 = __shfl_xor_sync(0xffffffffu, p2, o);
                    if (q1 < p1) p1 = q1;
                    if (q2 < p2) p2 = q2;
                }
                if ((lane & 3) == 0) {
                    atomicMin(&best[r1], p1);
                    atomicMin(&best[r1 + 8], p2);
                }
            }
            __syncthreads();
            // --- phase 2: flag near-min candidates (best only decreases, so
            // anything within eps of the FINAL min passes this test too) ---
            #pragma unroll
            for (int mt = 0; mt < 4; mt++) {
                const int r1 = wm * 64 + mt * 16 + (lane >> 2);
                const float s1 = srow[r1], s2 = srow[r1 + 8];
                const float b1 = __uint_as_float((uint32_t)(best[r1] >> 32))     + CAND_EPS;
                const float b2 = __uint_as_float((uint32_t)(best[r1 + 8] >> 32)) + CAND_EPS;
                #pragma unroll
                for (int gg = 0; gg < 8; gg++) {
                    const int c0 = wn * 64 + (gg >> 1) * 16 + ((gg & 1) << 3) + ((lane & 3) << 1);
                    const float w20 = w2p[c0], w21 = w2p[c0 + 1];
                    const uint32_t k0 = (uint32_t)(nb * 256 + c0);
                    float d0 = __fadd_rn(__fadd_rn(s1, __fmul_rn(-2.0f, acc[mt][gg][0])), w20);
                    float d1 = __fadd_rn(__fadd_rn(s1, __fmul_rn(-2.0f, acc[mt][gg][1])), w21);
                    float d2 = __fadd_rn(__fadd_rn(s2, __fmul_rn(-2.0f, acc[mt][gg][2])), w20);
                    float d3 = __fadd_rn(__fadd_rn(s2, __fmul_rn(-2.0f, acc[mt][gg][3])), w21);
                    if (d0 <= b1) { uint32_t s = atomicAdd(&ncnd[r1], 1u);     if (s < 16) cand[r1 * 16 + s] = k0; }
                    if (d1 <= b1) { uint32_t s = atomicAdd(&ncnd[r1], 1u);     if (s < 16) cand[r1 * 16 + s] = k0 + 1; }
                    if (d2 <= b2) { uint32_t s = atomicAdd(&ncnd[r1 + 8], 1u); if (s < 16) cand[(r1 + 8) * 16 + s] = k0; }
                    if (d3 <= b2) { uint32_t s = atomicAdd(&ncnd[r1 + 8], 1u); if (s < 16) cand[(r1 + 8) * 16 + s] = k0 + 1; }
                }
            }
        }
        __syncthreads();
    }

    if (tid < 128) {
        g_ncand[n0 + tid] = (int)min(ncnd[tid], 16u);
        #pragma unroll 4
        for (uint32_t c = 0; c < min(ncnd[tid], 16u); c++)
            g_cand[(size_t)(n0 + tid) * 16 + c] = cand[tid * 16 + c];
    }
}

// ---------------------------------------------------------------------------
// Argmin phase 2: exact re-arbitration of candidates with the R1 fp32 formula
// (sequential s, ascending-d fmaf t) — the arbiter that matched the reference.
__global__ void __launch_bounds__(256)
refine_kernel(const float* __restrict__ Z, const float* __restrict__ W) {
    const int row = blockIdx.x * blockDim.x + threadIdx.x;
    float z[DIM];
    const float4* zp = (const float4*)(Z + (size_t)row * DIM);
    #pragma unroll
    for (int i = 0; i < 16; i++) {
        float4 v = __ldg(zp + i);
        z[4 * i] = v.x; z[4 * i + 1] = v.y; z[4 * i + 2] = v.z; z[4 * i + 3] = v.w;
    }
    float s = 0.0f;
    #pragma unroll
    for (int d = 0; d < DIM; d++) s = __fadd_rn(s, __fmul_rn(z[d], z[d]));

    const int nc = g_ncand[row];
    unsigned long long bestp = ~0ull;
    for (int c = 0; c < nc; c++) {
        const uint32_t k = g_cand[(size_t)row * 16 + c];
        const float* wr = W + (size_t)k * DIM;
        float t = 0.0f;
        #pragma unroll
        for (int d = 0; d < DIM; d++) t = fmaf(z[d], __ldg(wr + d), t);
        float a    = __fadd_rn(s, __fmul_rn(-2.0f, t));
        float dist = __fadd_rn(a, g_w2[k]);
        unsigned long long q = ((unsigned long long)__float_as_uint(dist) << 32) | k;
        if (q < bestp) bestp = q;
    }
    g_idx[row] = (int)(unsigned)(bestp & 0xffffffffu);
}

// ---------------------------------------------------------------------------
// Epilogue: STE output, commitment partial sum, EMA accumulators.
__global__ void epilogue_kernel(const float* __restrict__ Z,
                                const float* __restrict__ W,
                                float* __restrict__ out, int out_size) {
    const int tid = threadIdx.x;
    const int r   = blockIdx.x * 4 + (tid >> 6);
    const int d   = tid & 63;
    const int ci  = g_idx[r];

    float ze = Z[(size_t)r * DIM + d];
    float q  = W[(size_t)ci * DIM + d];

    float st = __fadd_rn(ze, __fadd_rn(q, -ze));
    out[(size_t)r * DIM + d] = st;

    float diff = __fadd_rn(ze, -q);
    float sq   = __fmul_rn(diff, diff);

    __shared__ float red[256];
    red[tid] = sq;
    __syncthreads();
    #pragma unroll
    for (int o = 128; o > 0; o >>= 1) {
        if (tid < o) red[tid] += red[tid + o];
        __syncthreads();
    }
    if (tid == 0) atomicAdd(&g_loss, red[0]);

    atomicAdd(&g_avg[(size_t)ci * DIM + d], ze);
    if (d == 0) {
        atomicAdd(&g_cnt[ci], 1);
        if (out_size >= OFF_CNT) out[OFF_IDX + r] = (float)ci;
    }
}

// ---------------------------------------------------------------------------
__global__ void finalize_kernel(const float* __restrict__ ema_count,
                                const float* __restrict__ ema_avg,
                                float* __restrict__ out, int out_size) {
    const int t = blockIdx.x * blockDim.x + threadIdx.x;
    const float DEC = 0.99f;
    const float OMD = (float)(1.0 - 0.99);

    if (t == 0 && out_size > OFF_LOSS)
        out[OFF_LOSS] = __fmul_rn(0.25f, __fmul_rn(g_loss, 1.0f / 4194304.0f));
    if (t < KC && out_size >= OFF_CNT + KC)
        out[OFF_CNT + t] = __fadd_rn(__fmul_rn(ema_count[t], DEC),
                                     __fmul_rn(OMD, (float)g_cnt[t]));
    if (t < KC * DIM && out_size >= OUT_FULL)
        out[OFF_AVG + t] = __fadd_rn(__fmul_rn(ema_avg[t], DEC),
                                     __fmul_rn(OMD, g_avg[t]));
}

// ---------------------------------------------------------------------------
extern "C" void kernel_launch(void* const* d_in, const int* in_sizes, int n_in,
                              void* d_out, int out_size) {
    const float* Z         = (const float*)d_in[0];
    const float* W         = (const float*)d_in[1];
    const float* ema_count = (const float*)d_in[2];
    const float* ema_avg   = (const float*)d_in[3];
    float* out = (float*)d_out;

    cudaFuncSetAttribute(argmin_kernel,
                         cudaFuncAttributeMaxDynamicSharedMemorySize, SMEM_TOTAL);

    prep_kernel<<<768, 256>>>(W);
    argmin_kernel<<<NP / 128, 256, SMEM_TOTAL>>>(Z);
    refine_kernel<<<NP / 256, 256>>>(Z, W);
    epilogue_kernel<<<NP / 4, 256>>>(Z, W, out, out_size);
    finalize_kernel<<<(KC * DIM + 255) / 256, 256>>>(ema_count, ema_avg, out, out_size);
}